// round 1
// baseline (speedup 1.0000x reference)
#include <cuda_runtime.h>
#include <cstdint>

#define C_DIM  128
#define N_COMP 16
#define BM     64
#define THREADS 256

// ---- packed f32x2 helpers (sm_103a packed fp32 pipe) ----
__device__ __forceinline__ unsigned long long pack2(float lo, float hi) {
    unsigned long long r;
    asm("mov.b64 %0, {%1, %2};" : "=l"(r) : "f"(lo), "f"(hi));
    return r;
}
__device__ __forceinline__ void unpack2(unsigned long long v, float& lo, float& hi) {
    asm("mov.b64 {%0, %1}, %2;" : "=f"(lo), "=f"(hi) : "l"(v));
}
__device__ __forceinline__ unsigned long long fma2(unsigned long long a,
                                                   unsigned long long b,
                                                   unsigned long long c) {
    unsigned long long d;
    asm("fma.rn.f32x2 %0, %1, %2, %3;" : "=l"(d) : "l"(a), "l"(b), "l"(c));
    return d;
}

// One CTA: one l-value, BM=64 rows of that l, full 128-wide output.
// SMEM: Ws = W[l] * pw[l]  (128x128 f32, 64KB), Xs = 64x128 f32 (32KB).
// Thread tile: 4 rows x 8 cols (= 4 f32x2 accl pairs) -> 16 packed FMA / k-step.
__global__ __launch_bounds__(THREADS, 2)
void tp_linear_kernel(const float* __restrict__ x,
                      const float* __restrict__ w,
                      const float* __restrict__ pw,
                      float* __restrict__ out,
                      int n_nodes, int b1, int b2, int b3)
{
    extern __shared__ float smem[];
    float* Ws = smem;                    // 128*128
    float* Xs = smem + C_DIM * C_DIM;    // 64*128

    int tile = blockIdx.x;
    int l, tl;
    if (tile < b1)      { l = 0; tl = tile; }
    else if (tile < b2) { l = 1; tl = tile - b1; }
    else if (tile < b3) { l = 2; tl = tile - b2; }
    else                { l = 3; tl = tile - b3; }
    const int cl     = 2 * l + 1;   // components with this l
    const int mbase  = l * l;       // first component index for this l
    const int rows_l = n_nodes * cl;
    const int row0   = tl * BM;

    const int tid = threadIdx.x;
    const float scale = __ldg(&pw[l]);

    // ---- stage W[l] * pw[l] into shared (float4 vectorized) ----
    {
        const float4* w4  = (const float4*)(w + (size_t)l * C_DIM * C_DIM);
        float4* Ws4 = (float4*)Ws;
        #pragma unroll
        for (int i = tid; i < C_DIM * C_DIM / 4; i += THREADS) {
            float4 v = w4[i];
            v.x *= scale; v.y *= scale; v.z *= scale; v.w *= scale;
            Ws4[i] = v;
        }
    }

    // ---- stage 64 x-rows into shared (gathered by (node, m)) ----
    {
        float4* Xs4 = (float4*)Xs;
        const float4* x4 = (const float4*)x;
        #pragma unroll
        for (int idx = tid; idx < BM * (C_DIM / 4); idx += THREADS) {
            int lr = idx >> 5;        // local row (32 float4 per row)
            int v  = idx & 31;
            int r  = row0 + lr;       // row index within this l's row space
            float4 val = make_float4(0.f, 0.f, 0.f, 0.f);
            if (r < rows_l) {
                int node = r / cl;
                int m    = mbase + (r - node * cl);
                size_t grow = (size_t)node * N_COMP + m;
                val = x4[grow * (C_DIM / 4) + v];
            }
            Xs4[idx] = val;
        }
    }
    __syncthreads();

    const int tx = tid & 15;   // 16 threads cover 128 output cols (8 each)
    const int ty = tid >> 4;   // 16 thread-rows cover 64 rows (4 each)
    const int d0 = tx * 8;
    const int rb = ty * 4;

    unsigned long long acc[4][4];
    #pragma unroll
    for (int i = 0; i < 4; i++)
        #pragma unroll
        for (int j = 0; j < 4; j++)
            acc[i][j] = 0ull;

    #pragma unroll 4
    for (int c = 0; c < C_DIM; c++) {
        // W row slice, already pairs of packed f32 in shared (16B aligned)
        const ulonglong2* wr = (const ulonglong2*)(Ws + c * C_DIM + d0);
        ulonglong2 b01 = wr[0];
        ulonglong2 b23 = wr[1];
        unsigned long long bb0 = b01.x, bb1 = b01.y, bb2 = b23.x, bb3 = b23.y;

        unsigned long long aa[4];
        #pragma unroll
        for (int i = 0; i < 4; i++) {
            float a = Xs[(rb + i) * C_DIM + c];
            aa[i] = pack2(a, a);
        }

        #pragma unroll
        for (int i = 0; i < 4; i++) {
            acc[i][0] = fma2(aa[i], bb0, acc[i][0]);
            acc[i][1] = fma2(aa[i], bb1, acc[i][1]);
            acc[i][2] = fma2(aa[i], bb2, acc[i][2]);
            acc[i][3] = fma2(aa[i], bb3, acc[i][3]);
        }
    }

    // ---- write out (coalesced float4 pairs) ----
    #pragma unroll
    for (int i = 0; i < 4; i++) {
        int r = row0 + rb + i;
        if (r < rows_l) {
            int node = r / cl;
            int m    = mbase + (r - node * cl);
            size_t grow = (size_t)node * N_COMP + m;
            float4* o = (float4*)(out + grow * C_DIM + d0);
            float4 v0, v1;
            unpack2(acc[i][0], v0.x, v0.y);
            unpack2(acc[i][1], v0.z, v0.w);
            unpack2(acc[i][2], v1.x, v1.y);
            unpack2(acc[i][3], v1.z, v1.w);
            o[0] = v0;
            o[1] = v1;
        }
    }
}

extern "C" void kernel_launch(void* const* d_in, const int* in_sizes, int n_in,
                              void* d_out, int out_size) {
    const float* x  = (const float*)d_in[0];   // [N, 16, 128] f32
    const float* w  = (const float*)d_in[1];   // [4, 128, 128] f32
    const float* pw = (const float*)d_in[2];   // [4] f32
    float* out = (float*)d_out;

    const int n_nodes = in_sizes[0] / (N_COMP * C_DIM);

    // tiles per l (row counts n_nodes * {1,3,5,7})
    int t0 = (n_nodes * 1 + BM - 1) / BM;
    int t1 = (n_nodes * 3 + BM - 1) / BM;
    int t2 = (n_nodes * 5 + BM - 1) / BM;
    int t3 = (n_nodes * 7 + BM - 1) / BM;
    int b1 = t0, b2 = t0 + t1, b3 = t0 + t1 + t2;
    int grid = b3 + t3;

    size_t smem_bytes = (size_t)(C_DIM * C_DIM + BM * C_DIM) * sizeof(float); // 96KB
    cudaFuncSetAttribute(tp_linear_kernel,
                         cudaFuncAttributeMaxDynamicSharedMemorySize,
                         (int)smem_bytes);

    tp_linear_kernel<<<grid, THREADS, smem_bytes>>>(x, w, pw, out,
                                                    n_nodes, b1, b2, b3);
}